// round 2
// baseline (speedup 1.0000x reference)
#include <cuda_runtime.h>

// ---------------------------------------------------------------------------
// dsfa_former: (1) full causal attention + (2) Linformer attention
// Shapes (fixed): B=4, N=2048, H=8, D=32, KP=256
// R2: 2 queries per thread (i and i+128) -> halves smem traffic per FMA,
//     balancing the LDS crossbar (128B/cyc) against the FFMA pipe (2 inst/cyc).
// ---------------------------------------------------------------------------

constexpr int B  = 4;
constexpr int N  = 2048;
constexpr int H  = 8;
constexpr int D  = 32;
constexpr int KP = 256;

constexpr int ROW  = H * D;        // 256 floats per (b,n) row
constexpr int ROW4 = ROW / 4;      // 64 float4
constexpr int OUT_HALF = B * N * H * D;  // 2097152

__device__ float g_partial[8 * 2 * 32 * KP * D];  // [chunk][mat][bh][kk][e]
__device__ float g_kpvp[2 * 32 * KP * D];         // [mat][bh][kk][e]

__device__ __forceinline__ float dot4(float4 a, float4 b) {
    return fmaf(a.x, b.x, fmaf(a.y, b.y, fmaf(a.z, b.z, a.w * b.w)));
}
__device__ __forceinline__ float4 fma4(float s, float4 a, float4 c) {
    c.x = fmaf(s, a.x, c.x); c.y = fmaf(s, a.y, c.y);
    c.z = fmaf(s, a.z, c.z); c.w = fmaf(s, a.w, c.w);
    return c;
}
__device__ __forceinline__ float4 scl4(float4 a, float s) {
    a.x *= s; a.y *= s; a.z *= s; a.w *= s; return a;
}

// ---------------------------------------------------------------------------
// Kernel 1: full causal attention, 2 queries/thread (i, i+128).
// Block = 128 threads handles 256 queries. grid.x = 256 (8 qt x 32 bh),
// heavy diagonal tiles first.
// ---------------------------------------------------------------------------
__global__ void __launch_bounds__(128, 2)
full_attn_kernel(const float* __restrict__ Q, const float* __restrict__ K,
                 const float* __restrict__ V, float* __restrict__ out)
{
    __shared__ float4 Ks[128 * 8];
    __shared__ float4 Vs[128 * 8];

    const int bid = blockIdx.x;
    const int qt  = 7 - (bid >> 5);
    const int bh  = bid & 31;
    const int b   = bh >> 3, h = bh & 7;
    const int tid = threadIdx.x;
    const int ia  = qt * 256 + tid;        // query A
    const int ib  = ia + 128;              // query B (sets loop bound)
    const float scale = 0.17677669529663687f;

    const size_t base = (size_t)b * N * ROW + (size_t)h * D;
    const float4* Qg = (const float4*)(Q + base);
    const float4* Kg = (const float4*)(K + base);
    const float4* Vg = (const float4*)(V + base);

    const size_t qa = (size_t)ia * ROW4, qb = (size_t)ib * ROW4;
    float4 qa0 = Qg[qa+0], qa1 = Qg[qa+1], qa2 = Qg[qa+2], qa3 = Qg[qa+3];
    float4 qa4 = Qg[qa+4], qa5 = Qg[qa+5], qa6 = Qg[qa+6], qa7 = Qg[qa+7];
    float4 qb0 = Qg[qb+0], qb1 = Qg[qb+1], qb2 = Qg[qb+2], qb3 = Qg[qb+3];
    float4 qb4 = Qg[qb+4], qb5 = Qg[qb+5], qb6 = Qg[qb+6], qb7 = Qg[qb+7];

    float4 z = make_float4(0,0,0,0);
    float4 aa0=z,aa1=z,aa2=z,aa3=z,aa4=z,aa5=z,aa6=z,aa7=z;
    float4 ab0=z,ab1=z,ab2=z,ab3=z,ab4=z,ab5=z,ab6=z,ab7=z;
    float ma = -1e30f, la = 0.f;
    float mb = -1e30f, lb = 0.f;

    const int ntiles = 2 * qt + 2;
    for (int kt = 0; kt < ntiles; ++kt) {
        const int j0 = kt * 128;
        for (int f = tid; f < 1024; f += 128) {
            const int r = f >> 3, c = f & 7;
            const size_t g = (size_t)(j0 + r) * ROW4 + c;
            Ks[f] = Kg[g];
            Vs[f] = Vg[g];
        }
        __syncthreads();

        const int ja_lim = ia - j0;              // key jj valid for A iff jj <= ja_lim
        int jmax = ib - j0 + 1;                  // loop bound from query B
        if (jmax > 128) jmax = 128;
        for (int jj = 0; jj < jmax; ++jj) {
            const float4 k0=Ks[jj*8+0], k1=Ks[jj*8+1], k2=Ks[jj*8+2], k3=Ks[jj*8+3];
            const float4 k4=Ks[jj*8+4], k5=Ks[jj*8+5], k6=Ks[jj*8+6], k7=Ks[jj*8+7];

            float sa = ((dot4(qa0,k0)+dot4(qa1,k1)) + (dot4(qa2,k2)+dot4(qa3,k3)))
                     + ((dot4(qa4,k4)+dot4(qa5,k5)) + (dot4(qa6,k6)+dot4(qa7,k7)));
            float sb = ((dot4(qb0,k0)+dot4(qb1,k1)) + (dot4(qb2,k2)+dot4(qb3,k3)))
                     + ((dot4(qb4,k4)+dot4(qb5,k5)) + (dot4(qb6,k6)+dot4(qb7,k7)));
            sa *= scale; sb *= scale;
            if (jj > ja_lim) sa = -1e30f;        // causal mask for A (B always valid)

            if (sa > ma) {
                const float c = __expf(ma - sa);
                ma = sa; la *= c;
                aa0=scl4(aa0,c); aa1=scl4(aa1,c); aa2=scl4(aa2,c); aa3=scl4(aa3,c);
                aa4=scl4(aa4,c); aa5=scl4(aa5,c); aa6=scl4(aa6,c); aa7=scl4(aa7,c);
            }
            if (sb > mb) {
                const float c = __expf(mb - sb);
                mb = sb; lb *= c;
                ab0=scl4(ab0,c); ab1=scl4(ab1,c); ab2=scl4(ab2,c); ab3=scl4(ab3,c);
                ab4=scl4(ab4,c); ab5=scl4(ab5,c); ab6=scl4(ab6,c); ab7=scl4(ab7,c);
            }
            const float pa = __expf(sa - ma);
            const float pb = __expf(sb - mb);
            la += pa; lb += pb;

            const float4 v0=Vs[jj*8+0], v1=Vs[jj*8+1], v2=Vs[jj*8+2], v3=Vs[jj*8+3];
            const float4 v4=Vs[jj*8+4], v5=Vs[jj*8+5], v6=Vs[jj*8+6], v7=Vs[jj*8+7];
            aa0=fma4(pa,v0,aa0); aa1=fma4(pa,v1,aa1); aa2=fma4(pa,v2,aa2); aa3=fma4(pa,v3,aa3);
            aa4=fma4(pa,v4,aa4); aa5=fma4(pa,v5,aa5); aa6=fma4(pa,v6,aa6); aa7=fma4(pa,v7,aa7);
            ab0=fma4(pb,v0,ab0); ab1=fma4(pb,v1,ab1); ab2=fma4(pb,v2,ab2); ab3=fma4(pb,v3,ab3);
            ab4=fma4(pb,v4,ab4); ab5=fma4(pb,v5,ab5); ab6=fma4(pb,v6,ab6); ab7=fma4(pb,v7,ab7);
        }
        __syncthreads();
    }

    float4* Og = (float4*)(out + base);
    const float iva = 1.0f / la, ivb = 1.0f / lb;
    Og[qa+0]=scl4(aa0,iva); Og[qa+1]=scl4(aa1,iva); Og[qa+2]=scl4(aa2,iva); Og[qa+3]=scl4(aa3,iva);
    Og[qa+4]=scl4(aa4,iva); Og[qa+5]=scl4(aa5,iva); Og[qa+6]=scl4(aa6,iva); Og[qa+7]=scl4(aa7,iva);
    Og[qb+0]=scl4(ab0,ivb); Og[qb+1]=scl4(ab1,ivb); Og[qb+2]=scl4(ab2,ivb); Og[qb+3]=scl4(ab3,ivb);
    Og[qb+4]=scl4(ab4,ivb); Og[qb+5]=scl4(ab5,ivb); Og[qb+6]=scl4(ab6,ivb); Og[qb+7]=scl4(ab7,ivb);
}

// ---------------------------------------------------------------------------
// Kernel 2: Linformer projections Kp = E^T K_b, Vp = F^T V_b (unchanged).
// ---------------------------------------------------------------------------
__global__ void __launch_bounds__(256)
proj_kernel(const float* __restrict__ K, const float* __restrict__ V,
            const float* __restrict__ E, const float* __restrict__ F)
{
    __shared__ float4 Xs[64 * 8];
    const int bh = blockIdx.x, mat = blockIdx.y, chunk = blockIdx.z;
    const int b = bh >> 3, h = bh & 7;
    const int kk = threadIdx.x;

    const float* X = mat ? V : K;
    const float* P = mat ? F : E;
    const float4* Xg = (const float4*)(X + (size_t)b * N * ROW + (size_t)h * D);

    float4 acc[8];
#pragma unroll
    for (int r = 0; r < 8; ++r) acc[r] = make_float4(0,0,0,0);

    for (int t = 0; t < 4; ++t) {
        const int n0 = chunk * 256 + t * 64;
        for (int f = threadIdx.x; f < 512; f += 256) {
            const int r = f >> 3, c = f & 7;
            Xs[f] = Xg[(size_t)(n0 + r) * ROW4 + c];
        }
        __syncthreads();
#pragma unroll 4
        for (int nn = 0; nn < 64; ++nn) {
            const float ev = __ldg(&P[(size_t)(n0 + nn) * KP + kk]);
            const float4* xr = &Xs[nn * 8];
#pragma unroll
            for (int r = 0; r < 8; ++r) acc[r] = fma4(ev, xr[r], acc[r]);
        }
        __syncthreads();
    }

    float4* pp = (float4*)g_partial +
                 ((size_t)((chunk * 2 + mat) * 32 + bh) * KP + kk) * 8;
#pragma unroll
    for (int r = 0; r < 8; ++r) pp[r] = acc[r];
}

__global__ void reduce_kernel()
{
    const int idx = blockIdx.x * 256 + threadIdx.x;
    const float4* p = (const float4*)g_partial;
    float4 s = p[idx];
#pragma unroll
    for (int c = 1; c < 8; ++c) {
        const float4 t = p[(size_t)c * 131072 + idx];
        s.x += t.x; s.y += t.y; s.z += t.z; s.w += t.w;
    }
    ((float4*)g_kpvp)[idx] = s;
}

// ---------------------------------------------------------------------------
// Kernel 3: Linformer attention, 2 queries/thread (n, n+128).
// Block = 128 threads handles 256 queries; grid (32 bh, 8 nt).
// ---------------------------------------------------------------------------
__global__ void __launch_bounds__(128, 2)
lin_attn_kernel(const float* __restrict__ Q, float* __restrict__ out)
{
    __shared__ float4 Kps[128 * 8];
    __shared__ float4 Vps[128 * 8];

    const int bh = blockIdx.x, nt = blockIdx.y;
    const int b = bh >> 3, h = bh & 7;
    const int tid = threadIdx.x;
    const int na = nt * 256 + tid;
    const float scale = 0.17677669529663687f;

    const size_t base = (size_t)b * N * ROW + (size_t)h * D;
    const float4* Qg  = (const float4*)(Q + base);
    const float4* Kpg = (const float4*)g_kpvp + (size_t)bh * (KP * 8);
    const float4* Vpg = (const float4*)g_kpvp + (size_t)(32 + bh) * (KP * 8);

    const size_t qa = (size_t)na * ROW4, qb = qa + (size_t)128 * ROW4;
    float4 qa0 = Qg[qa+0], qa1 = Qg[qa+1], qa2 = Qg[qa+2], qa3 = Qg[qa+3];
    float4 qa4 = Qg[qa+4], qa5 = Qg[qa+5], qa6 = Qg[qa+6], qa7 = Qg[qa+7];
    float4 qb0 = Qg[qb+0], qb1 = Qg[qb+1], qb2 = Qg[qb+2], qb3 = Qg[qb+3];
    float4 qb4 = Qg[qb+4], qb5 = Qg[qb+5], qb6 = Qg[qb+6], qb7 = Qg[qb+7];

    float4 z = make_float4(0,0,0,0);
    float4 aa0=z,aa1=z,aa2=z,aa3=z,aa4=z,aa5=z,aa6=z,aa7=z;
    float4 ab0=z,ab1=z,ab2=z,ab3=z,ab4=z,ab5=z,ab6=z,ab7=z;
    float ma = -1e30f, la = 0.f;
    float mb = -1e30f, lb = 0.f;

    for (int half = 0; half < 2; ++half) {
        for (int f = tid; f < 1024; f += 128) {
            Kps[f] = Kpg[half * 1024 + f];
            Vps[f] = Vpg[half * 1024 + f];
        }
        __syncthreads();
        for (int kk = 0; kk < 128; ++kk) {
            const float4 k0=Kps[kk*8+0], k1=Kps[kk*8+1], k2=Kps[kk*8+2], k3=Kps[kk*8+3];
            const float4 k4=Kps[kk*8+4], k5=Kps[kk*8+5], k6=Kps[kk*8+6], k7=Kps[kk*8+7];

            float sa = ((dot4(qa0,k0)+dot4(qa1,k1)) + (dot4(qa2,k2)+dot4(qa3,k3)))
                     + ((dot4(qa4,k4)+dot4(qa5,k5)) + (dot4(qa6,k6)+dot4(qa7,k7)));
            float sb = ((dot4(qb0,k0)+dot4(qb1,k1)) + (dot4(qb2,k2)+dot4(qb3,k3)))
                     + ((dot4(qb4,k4)+dot4(qb5,k5)) + (dot4(qb6,k6)+dot4(qb7,k7)));
            sa *= scale; sb *= scale;

            if (sa > ma) {
                const float c = __expf(ma - sa);
                ma = sa; la *= c;
                aa0=scl4(aa0,c); aa1=scl4(aa1,c); aa2=scl4(aa2,c); aa3=scl4(aa3,c);
                aa4=scl4(aa4,c); aa5=scl4(aa5,c); aa6=scl4(aa6,c); aa7=scl4(aa7,c);
            }
            if (sb > mb) {
                const float c = __expf(mb - sb);
                mb = sb; lb *= c;
                ab0=scl4(ab0,c); ab1=scl4(ab1,c); ab2=scl4(ab2,c); ab3=scl4(ab3,c);
                ab4=scl4(ab4,c); ab5=scl4(ab5,c); ab6=scl4(ab6,c); ab7=scl4(ab7,c);
            }
            const float pa = __expf(sa - ma);
            const float pb = __expf(sb - mb);
            la += pa; lb += pb;

            const float4 v0=Vps[kk*8+0], v1=Vps[kk*8+1], v2=Vps[kk*8+2], v3=Vps[kk*8+3];
            const float4 v4=Vps[kk*8+4], v5=Vps[kk*8+5], v6=Vps[kk*8+6], v7=Vps[kk*8+7];
            aa0=fma4(pa,v0,aa0); aa1=fma4(pa,v1,aa1); aa2=fma4(pa,v2,aa2); aa3=fma4(pa,v3,aa3);
            aa4=fma4(pa,v4,aa4); aa5=fma4(pa,v5,aa5); aa6=fma4(pa,v6,aa6); aa7=fma4(pa,v7,aa7);
            ab0=fma4(pb,v0,ab0); ab1=fma4(pb,v1,ab1); ab2=fma4(pb,v2,ab2); ab3=fma4(pb,v3,ab3);
            ab4=fma4(pb,v4,ab4); ab5=fma4(pb,v5,ab5); ab6=fma4(pb,v6,ab6); ab7=fma4(pb,v7,ab7);
        }
        __syncthreads();
    }

    float4* Og = (float4*)(out + base);
    const float iva = 1.0f / la, ivb = 1.0f / lb;
    Og[qa+0]=scl4(aa0,iva); Og[qa+1]=scl4(aa1,iva); Og[qa+2]=scl4(aa2,iva); Og[qa+3]=scl4(aa3,iva);
    Og[qa+4]=scl4(aa4,iva); Og[qa+5]=scl4(aa5,iva); Og[qa+6]=scl4(aa6,iva); Og[qa+7]=scl4(aa7,iva);
    Og[qb+0]=scl4(ab0,ivb); Og[qb+1]=scl4(ab1,ivb); Og[qb+2]=scl4(ab2,ivb); Og[qb+3]=scl4(ab3,ivb);
    Og[qb+4]=scl4(ab4,ivb); Og[qb+5]=scl4(ab5,ivb); Og[qb+6]=scl4(ab6,ivb); Og[qb+7]=scl4(ab7,ivb);
}

// ---------------------------------------------------------------------------
extern "C" void kernel_launch(void* const* d_in, const int* in_sizes, int n_in,
                              void* d_out, int out_size)
{
    const float* Q = (const float*)d_in[0];
    const float* K = (const float*)d_in[1];
    const float* V = (const float*)d_in[2];
    const float* E = (const float*)d_in[3];
    const float* F = (const float*)d_in[4];
    float* out = (float*)d_out;

    proj_kernel<<<dim3(32, 2, 8), 256>>>(K, V, E, F);
    reduce_kernel<<<512, 256>>>();
    full_attn_kernel<<<256, 128>>>(Q, K, V, out);             // out_full
    lin_attn_kernel<<<dim3(32, 8), 128>>>(Q, out + OUT_HALF); // out_lin
}

// round 3
// speedup vs baseline: 1.2272x; 1.2272x over previous
#include <cuda_runtime.h>

// ---------------------------------------------------------------------------
// dsfa_former: (1) full causal attention + (2) Linformer attention
// Shapes (fixed): B=4, N=2048, H=8, D=32, KP=256
// R3: R1 structure (1 query/thread, good occupancy) + packed fma.rn.f32x2
//     (FFMA2) for all dot products / accumulations -> 2 FLOPs per fma-pipe slot.
// ---------------------------------------------------------------------------

typedef unsigned long long u64;

constexpr int B  = 4;
constexpr int N  = 2048;
constexpr int H  = 8;
constexpr int D  = 32;
constexpr int KP = 256;

constexpr int ROW  = H * D;        // 256 floats per (b,n) row
constexpr int ROW4 = ROW / 4;      // 64 float4
constexpr int OUT_HALF = B * N * H * D;

__device__ float g_partial[8 * 2 * 32 * KP * D];
__device__ float g_kpvp[2 * 32 * KP * D];

__device__ __forceinline__ u64 pk2(float lo, float hi) {
    u64 r; asm("mov.b64 %0, {%1, %2};" : "=l"(r) : "f"(lo), "f"(hi)); return r;
}
__device__ __forceinline__ u64 fma2(u64 a, u64 b, u64 c) {
    u64 d; asm("fma.rn.f32x2 %0, %1, %2, %3;" : "=l"(d) : "l"(a), "l"(b), "l"(c)); return d;
}
__device__ __forceinline__ u64 mul2(u64 a, u64 b) {
    u64 d; asm("mul.rn.f32x2 %0, %1, %2;" : "=l"(d) : "l"(a), "l"(b)); return d;
}
__device__ __forceinline__ u64 add2(u64 a, u64 b) {
    u64 d; asm("add.rn.f32x2 %0, %1, %2;" : "=l"(d) : "l"(a), "l"(b)); return d;
}
__device__ __forceinline__ float2 up2(u64 a) {
    float2 v; asm("mov.b64 {%0, %1}, %2;" : "=f"(v.x), "=f"(v.y) : "l"(a)); return v;
}

// load 8 float4 (one D=32 row) from smem as 16 packed f32x2
__device__ __forceinline__ void load_row16(const float4* src, u64* p) {
#pragma unroll
    for (int r = 0; r < 8; ++r) {
        const ulonglong2 t = ((const ulonglong2*)src)[r];
        p[2*r] = t.x; p[2*r+1] = t.y;
    }
}
// dot of two 16-pair vectors -> scalar
__device__ __forceinline__ float dot16(const u64* a, const u64* b) {
    u64 s0 = 0, s1 = 0, s2 = 0, s3 = 0;
#pragma unroll
    for (int r = 0; r < 4; ++r) {
        s0 = fma2(a[4*r+0], b[4*r+0], s0);
        s1 = fma2(a[4*r+1], b[4*r+1], s1);
        s2 = fma2(a[4*r+2], b[4*r+2], s2);
        s3 = fma2(a[4*r+3], b[4*r+3], s3);
    }
    const float2 t = up2(add2(add2(s0, s1), add2(s2, s3)));
    return t.x + t.y;
}

// ---------------------------------------------------------------------------
// Kernel 1: full causal attention. 1 thread = 1 query row, f32x2 math.
// ---------------------------------------------------------------------------
__global__ void __launch_bounds__(256, 2)
full_attn_kernel(const float* __restrict__ Q, const float* __restrict__ K,
                 const float* __restrict__ V, float* __restrict__ out)
{
    __shared__ float4 Ks[128 * 8];
    __shared__ float4 Vs[128 * 8];

    const int bid = blockIdx.x;
    const int qt  = 7 - (bid >> 5);
    const int bh  = bid & 31;
    const int b   = bh >> 3, h = bh & 7;
    const int tid = threadIdx.x;
    const int i   = qt * 256 + tid;
    const float scale = 0.17677669529663687f;

    const size_t base = (size_t)b * N * ROW + (size_t)h * D;
    const float4* Qg = (const float4*)(Q + base);
    const float4* Kg = (const float4*)(K + base);
    const float4* Vg = (const float4*)(V + base);

    const size_t qoff = (size_t)i * ROW4;
    u64 q[16];
#pragma unroll
    for (int r = 0; r < 8; ++r) {
        const float4 t = Qg[qoff + r];
        q[2*r]   = pk2(t.x, t.y);
        q[2*r+1] = pk2(t.z, t.w);
    }

    u64 acc[16];
#pragma unroll
    for (int r = 0; r < 16; ++r) acc[r] = 0ull;
    float m = -1e30f, l = 0.f;

    const int ntiles = 2 * qt + 2;
    for (int kt = 0; kt < ntiles; ++kt) {
        const int j0 = kt * 128;
        for (int f = tid; f < 1024; f += 256) {
            const int r = f >> 3, c = f & 7;
            const size_t g = (size_t)(j0 + r) * ROW4 + c;
            Ks[f] = Kg[g];
            Vs[f] = Vg[g];
        }
        __syncthreads();

        int jmax = i - j0 + 1;
        if (jmax > 128) jmax = 128;
        for (int jj = 0; jj < jmax; ++jj) {
            u64 k[16];
            load_row16(&Ks[jj * 8], k);
            const float sl = dot16(q, k) * scale;

            if (sl > m) {
                const u64 cc = pk2(__expf(m - sl), __expf(m - sl));
                l *= up2(cc).x;
                m = sl;
#pragma unroll
                for (int r = 0; r < 16; ++r) acc[r] = mul2(acc[r], cc);
            }
            const float p = __expf(sl - m);
            l += p;
            const u64 pp = pk2(p, p);

            u64 v[16];
            load_row16(&Vs[jj * 8], v);
#pragma unroll
            for (int r = 0; r < 16; ++r) acc[r] = fma2(pp, v[r], acc[r]);
        }
        __syncthreads();
    }

    const float inv = 1.0f / l;
    const u64 iv = pk2(inv, inv);
    float4* Og = (float4*)(out + base);
#pragma unroll
    for (int r = 0; r < 8; ++r) {
        const float2 lo = up2(mul2(acc[2*r], iv));
        const float2 hi = up2(mul2(acc[2*r+1], iv));
        Og[qoff + r] = make_float4(lo.x, lo.y, hi.x, hi.y);
    }
}

// ---------------------------------------------------------------------------
// Kernel 2: Linformer projections Kp = E^T K_b, Vp = F^T V_b (f32x2 math).
// ---------------------------------------------------------------------------
__global__ void __launch_bounds__(256)
proj_kernel(const float* __restrict__ K, const float* __restrict__ V,
            const float* __restrict__ E, const float* __restrict__ F)
{
    __shared__ float4 Xs[64 * 8];
    const int bh = blockIdx.x, mat = blockIdx.y, chunk = blockIdx.z;
    const int b = bh >> 3, h = bh & 7;
    const int kk = threadIdx.x;

    const float* X = mat ? V : K;
    const float* P = mat ? F : E;
    const float4* Xg = (const float4*)(X + (size_t)b * N * ROW + (size_t)h * D);

    u64 acc[16];
#pragma unroll
    for (int r = 0; r < 16; ++r) acc[r] = 0ull;

    for (int t = 0; t < 4; ++t) {
        const int n0 = chunk * 256 + t * 64;
        for (int f = threadIdx.x; f < 512; f += 256) {
            const int r = f >> 3, c = f & 7;
            Xs[f] = Xg[(size_t)(n0 + r) * ROW4 + c];
        }
        __syncthreads();
#pragma unroll 4
        for (int nn = 0; nn < 64; ++nn) {
            const float ev = __ldg(&P[(size_t)(n0 + nn) * KP + kk]);
            const u64 e2 = pk2(ev, ev);
            const ulonglong2* xr = (const ulonglong2*)&Xs[nn * 8];
#pragma unroll
            for (int r = 0; r < 8; ++r) {
                const ulonglong2 x = xr[r];
                acc[2*r]   = fma2(e2, x.x, acc[2*r]);
                acc[2*r+1] = fma2(e2, x.y, acc[2*r+1]);
            }
        }
        __syncthreads();
    }

    ulonglong2* pp = (ulonglong2*)((float4*)g_partial +
                 ((size_t)((chunk * 2 + mat) * 32 + bh) * KP + kk) * 8);
#pragma unroll
    for (int r = 0; r < 8; ++r) pp[r] = make_ulonglong2(acc[2*r], acc[2*r+1]);
}

__global__ void reduce_kernel()
{
    const int idx = blockIdx.x * 256 + threadIdx.x;
    const float4* p = (const float4*)g_partial;
    float4 s = p[idx];
#pragma unroll
    for (int c = 1; c < 8; ++c) {
        const float4 t = p[(size_t)c * 131072 + idx];
        s.x += t.x; s.y += t.y; s.z += t.z; s.w += t.w;
    }
    ((float4*)g_kpvp)[idx] = s;
}

// ---------------------------------------------------------------------------
// Kernel 3: Linformer attention. 1 thread = 1 query row, f32x2 math.
// ---------------------------------------------------------------------------
__global__ void __launch_bounds__(256, 2)
lin_attn_kernel(const float* __restrict__ Q, float* __restrict__ out)
{
    __shared__ float4 Kps[128 * 8];
    __shared__ float4 Vps[128 * 8];

    const int bh = blockIdx.x, nt = blockIdx.y;
    const int b = bh >> 3, h = bh & 7;
    const int tid = threadIdx.x;
    const int n = nt * 256 + tid;
    const float scale = 0.17677669529663687f;

    const size_t base = (size_t)b * N * ROW + (size_t)h * D;
    const float4* Qg  = (const float4*)(Q + base);
    const float4* Kpg = (const float4*)g_kpvp + (size_t)bh * (KP * 8);
    const float4* Vpg = (const float4*)g_kpvp + (size_t)(32 + bh) * (KP * 8);

    const size_t qoff = (size_t)n * ROW4;
    u64 q[16];
#pragma unroll
    for (int r = 0; r < 8; ++r) {
        const float4 t = Qg[qoff + r];
        q[2*r]   = pk2(t.x, t.y);
        q[2*r+1] = pk2(t.z, t.w);
    }

    u64 acc[16];
#pragma unroll
    for (int r = 0; r < 16; ++r) acc[r] = 0ull;
    float m = -1e30f, l = 0.f;

    for (int half = 0; half < 2; ++half) {
        for (int f = tid; f < 1024; f += 256) {
            Kps[f] = Kpg[half * 1024 + f];
            Vps[f] = Vpg[half * 1024 + f];
        }
        __syncthreads();
        for (int kk = 0; kk < 128; ++kk) {
            u64 k[16];
            load_row16(&Kps[kk * 8], k);
            const float sl = dot16(q, k) * scale;

            if (sl > m) {
                const float c = __expf(m - sl);
                const u64 cc = pk2(c, c);
                l *= c;
                m = sl;
#pragma unroll
                for (int r = 0; r < 16; ++r) acc[r] = mul2(acc[r], cc);
            }
            const float p = __expf(sl - m);
            l += p;
            const u64 pp = pk2(p, p);

            u64 v[16];
            load_row16(&Vps[kk * 8], v);
#pragma unroll
            for (int r = 0; r < 16; ++r) acc[r] = fma2(pp, v[r], acc[r]);
        }
        __syncthreads();
    }

    const float inv = 1.0f / l;
    const u64 iv = pk2(inv, inv);
    float4* Og = (float4*)(out + base);
#pragma unroll
    for (int r = 0; r < 8; ++r) {
        const float2 lo = up2(mul2(acc[2*r], iv));
        const float2 hi = up2(mul2(acc[2*r+1], iv));
        Og[qoff + r] = make_float4(lo.x, lo.y, hi.x, hi.y);
    }
}

// ---------------------------------------------------------------------------
extern "C" void kernel_launch(void* const* d_in, const int* in_sizes, int n_in,
                              void* d_out, int out_size)
{
    const float* Q = (const float*)d_in[0];
    const float* K = (const float*)d_in[1];
    const float* V = (const float*)d_in[2];
    const float* E = (const float*)d_in[3];
    const float* F = (const float*)d_in[4];
    float* out = (float*)d_out;

    proj_kernel<<<dim3(32, 2, 8), 256>>>(K, V, E, F);
    reduce_kernel<<<512, 256>>>();
    full_attn_kernel<<<256, 256>>>(Q, K, V, out);             // out_full
    lin_attn_kernel<<<dim3(32, 8), 256>>>(Q, out + OUT_HALF); // out_lin
}